// round 10
// baseline (speedup 1.0000x reference)
#include <cuda_runtime.h>
#include <math.h>

// Problem constants
#define WE   300      // word embedding dim
#define DEm  256      // doc embedding dim
#define NV   50000    // vocab
#define NDn  100000   // num docs
#define NB   4096     // batch
#define NGw  10       // words per bag
#define NZ   10       // negatives
#define NENT (NB * 11)      // 45056 (b, slot) -> doc entries
#define NBKT (NDn / 32)     // 3125 doc buckets (32 cols each)

#define PT_BLOCKS  ((WE*DEm)/256)   // 300
#define ST_BLOCKS  256

// ---------------- scratch (device globals; no allocation) ----------------
__device__ __align__(16) float g_rvT[(size_t)NV * WE];   // 60 MB
__device__ __align__(16) float g_projT[WE * DEm];        // 300 x 256 (k-major)
__device__ __align__(16) float g_gNT[NB * WE];           // 4096 x 300
__device__ __align__(16) float g_Ct[NB * DEm];           // t_pre^T: 4096 x 256
__device__ __align__(16) float g_T[NB * DEm];            // clipped t: 4096 x 256 (4 MB)
__device__ int   g_bcnt[NBKT];
__device__ int   g_boff[NBKT + 1];
__device__ int   g_bcur[NBKT];
__device__ int   g_bent[NENT];
__device__ float g_dots[NENT];
__device__ float g_ps [ST_BLOCKS * DEm];
__device__ float g_pss[ST_BLOCKS * DEm];
__device__ float g_mean[DEm];
__device__ float g_factor[DEm];
__device__ float g_lpw[NB];
__device__ float g_regpart[NBKT];
__device__ float g_projsq[PT_BLOCKS];

__device__ __forceinline__ float warpSum(float v) {
#pragma unroll
    for (int o = 16; o; o >>= 1) v += __shfl_down_sync(0xffffffffu, v, o);
    return v;
}
__device__ __forceinline__ float log_sig(float x) {
    return (x >= 0.f) ? -log1pf(expf(-x)) : x - log1pf(expf(x));
}

// ================= CSR bucket build (ids only; tiny) =======================
__global__ void __launch_bounds__(256) k_bzero() {
    int i = blockIdx.x * 256 + threadIdx.x;
    if (i < NBKT) g_bcnt[i] = 0;
}
__global__ void __launch_bounds__(256)
k_bcount(const int* __restrict__ doc_ids, const int* __restrict__ neg_ids) {
    int i = blockIdx.x * 256 + threadIdx.x;
    if (i >= NENT) return;
    int doc = (i < NB) ? doc_ids[i] : neg_ids[i - NB];
    atomicAdd(&g_bcnt[doc >> 5], 1);
}
__global__ void __launch_bounds__(1024) k_bscan() {
    const int T = 1024, CH = (NBKT + T - 1) / T;   // 4
    __shared__ int s[T];
    int t = threadIdx.x;
    int base = t * CH;
    int sum = 0;
#pragma unroll 1
    for (int i = 0; i < CH; i++) {
        int v = base + i;
        if (v < NBKT) sum += g_bcnt[v];
    }
    s[t] = sum;
    __syncthreads();
    for (int o = 1; o < T; o <<= 1) {
        int x = (t >= o) ? s[t - o] : 0;
        __syncthreads();
        s[t] += x;
        __syncthreads();
    }
    int run = s[t] - sum;
#pragma unroll 1
    for (int i = 0; i < CH; i++) {
        int v = base + i;
        if (v < NBKT) {
            g_boff[v] = run;
            g_bcur[v] = run;
            run += g_bcnt[v];
        }
    }
    if (t == T - 1) g_boff[NBKT] = s[T - 1];
}
__global__ void __launch_bounds__(256)
k_bfill(const int* __restrict__ doc_ids, const int* __restrict__ neg_ids) {
    int i = blockIdx.x * 256 + threadIdx.x;
    if (i >= NENT) return;
    int b, v, doc;
    if (i < NB) { b = i; v = 0; doc = doc_ids[i]; }
    else {
        int j = i - NB;
        b = j / NZ; v = 1 + (j % NZ); doc = neg_ids[j];
    }
    int pos = atomicAdd(&g_bcur[doc >> 5], 1);
    g_bent[pos] = ((doc & 31) << 16) | (b * 11 + v);
}

// ================= main chain ==============================================
// K0: transpose proj + partial sum(proj^2)
__global__ void __launch_bounds__(256) k_pt(const float* __restrict__ proj) {
    int idx = blockIdx.x * 256 + threadIdx.x;
    int k = idx >> 8, m = idx & 255;
    float v = proj[m * WE + k];
    g_projT[idx] = v;
    float s = warpSum(v * v);
    __shared__ float red[8];
    if ((threadIdx.x & 31) == 0) red[threadIdx.x >> 5] = s;
    __syncthreads();
    if (threadIdx.x == 0) {
        float t = 0.f;
#pragma unroll
        for (int i = 0; i < 8; i++) t += red[i];
        g_projsq[blockIdx.x] = t;
    }
}

// K1: transpose rv (300 x 50000 -> 50000 x 300)
__global__ void __launch_bounds__(256) k_trv(const float* __restrict__ rv) {
    __shared__ float t[32][33];
    int x0 = blockIdx.x * 32, y0 = blockIdx.y * 32;
    int tx = threadIdx.x, ty = threadIdx.y;       // (32, 8)
#pragma unroll
    for (int j = 0; j < 32; j += 8) {
        int r = y0 + ty + j, c = x0 + tx;
        t[ty + j][tx] = (r < WE && c < NV) ? rv[(size_t)r * NV + c] : 0.f;
    }
    __syncthreads();
#pragma unroll
    for (int j = 0; j < 32; j += 8) {
        int c = x0 + ty + j, r = y0 + tx;
        if (c < NV && r < WE) g_rvT[(size_t)c * WE + r] = t[tx][ty + j];
    }
}

// K2: gather 10 word rows of rvT, mean, L2-normalize
__global__ void __launch_bounds__(320) k_gather(const int* __restrict__ word_ids) {
    int b = blockIdx.x;
    int tid = threadIdx.x;                 // 320 threads
    __shared__ int   wid[NGw];
    __shared__ float red[10];
    __shared__ float rinv;
    if (tid < NGw) wid[tid] = word_ids[b * NGw + tid];
    __syncthreads();
    float g = 0.f;
    if (tid < WE) {
#pragma unroll
        for (int j = 0; j < NGw; j++) g += __ldg(&g_rvT[(size_t)wid[j] * WE + tid]);
        g *= 0.1f;
    }
    float s = warpSum(g * g);
    if ((tid & 31) == 0) red[tid >> 5] = s;
    __syncthreads();
    if (tid == 0) {
        float t = 0.f;
#pragma unroll
        for (int i = 0; i < 10; i++) t += red[i];
        rinv = rsqrtf(t);
    }
    __syncthreads();
    if (tid < WE) g_gNT[b * WE + tid] = g * rinv;
}

// K3: SGEMM  Ct[n][m] = sum_k gNT[n][k] * projT[k][m]
__global__ void __launch_bounds__(256) k_gemm() {
    __shared__ float Asm[20][68];
    __shared__ float Bs[20][64];
    int tid = threadIdx.x;
    int tm = tid >> 4, tn = tid & 15;
    int n0 = blockIdx.x * 64, m0 = blockIdx.y * 64;
    float acc[4][4] = {};
    for (int k0 = 0; k0 < WE; k0 += 20) {
        for (int i = tid; i < 320; i += 256) {
            int row = i / 5, kq = i % 5;
            float4 v = *(const float4*)&g_gNT[(n0 + row) * WE + k0 + kq * 4];
            Asm[kq * 4 + 0][row] = v.x;
            Asm[kq * 4 + 1][row] = v.y;
            Asm[kq * 4 + 2][row] = v.z;
            Asm[kq * 4 + 3][row] = v.w;
        }
        for (int i = tid; i < 320; i += 256) {
            int row = i >> 4, q = i & 15;
            *(float4*)&Bs[row][q * 4] =
                *(const float4*)&g_projT[(k0 + row) * DEm + m0 + q * 4];
        }
        __syncthreads();
#pragma unroll
        for (int k = 0; k < 20; k++) {
            float4 a = *(const float4*)&Asm[k][tm * 4];
            float4 b = *(const float4*)&Bs[k][tn * 4];
            float an[4] = {a.x, a.y, a.z, a.w};
            float bm[4] = {b.x, b.y, b.z, b.w};
#pragma unroll
            for (int j = 0; j < 4; j++)
#pragma unroll
                for (int i = 0; i < 4; i++) acc[j][i] += bm[j] * an[i];
        }
        __syncthreads();
    }
#pragma unroll
    for (int i = 0; i < 4; i++) {
        int n = n0 + tm * 4 + i;
        *(float4*)&g_Ct[n * DEm + m0 + tn * 4] =
            make_float4(acc[0][i], acc[1][i], acc[2][i], acc[3][i]);
    }
}

// K4a/K4b: batch-norm stats
__global__ void __launch_bounds__(256) k_stats1() {
    int m = threadIdx.x;
    int nb = blockIdx.x * (NB / ST_BLOCKS);
    float s = 0.f, ss = 0.f;
#pragma unroll
    for (int i = 0; i < NB / ST_BLOCKS; i++) {
        float x = g_Ct[(nb + i) * DEm + m];
        s += x; ss += x * x;
    }
    g_ps [blockIdx.x * DEm + m] = s;
    g_pss[blockIdx.x * DEm + m] = ss;
}
__global__ void __launch_bounds__(256) k_stats2() {
    int m = threadIdx.x;
    float s = 0.f, ss = 0.f;
#pragma unroll 1
    for (int j = 0; j < ST_BLOCKS; j++) {
        s  += g_ps [j * DEm + m];
        ss += g_pss[j * DEm + m];
    }
    float mean = s * (1.0f / NB);
    float var  = fmaxf((ss - (float)NB * mean * mean) * (1.0f / (NB - 1)), 0.f);
    g_mean[m]   = mean;
    g_factor[m] = rsqrtf(sqrtf(var));   // 1/sqrt(std), std ddof=1
}

// K5: materialize clipped t matrix g_T[b][d] (4 MB, stays in L2)
__global__ void __launch_bounds__(256) k_tmat(const float* __restrict__ beta) {
    int b = blockIdx.x, d = threadIdx.x;
    float x = g_Ct[b * DEm + d];
    g_T[b * DEm + d] =
        fminf(fmaxf((x - g_mean[d]) * g_factor[d] + beta[d], -1.f), 1.f);
}

// K6: FUSED rd pass — one coalesced read of rd; sum(rd^2) partials; and all
// dot-products for entries whose doc falls in this block's 32 columns.
__global__ void __launch_bounds__(256) k_fused(const float* __restrict__ rd) {
    __shared__ float tile[DEm][33];     // [d][c], conflict-free both phases
    int c0 = blockIdx.x * 32;
    int tx = threadIdx.x & 31;
    int ty = threadIdx.x >> 5;          // warp id 0..7
    float ss = 0.f;
#pragma unroll
    for (int d0 = 0; d0 < DEm; d0 += 8) {
        float v = __ldg(&rd[(size_t)(d0 + ty) * NDn + c0 + tx]);
        tile[d0 + ty][tx] = v;
        ss += v * v;
    }
    // block reduction of ss (overlaps with nothing critical)
    ss = warpSum(ss);
    __shared__ float red[8];
    if (tx == 0) red[ty] = ss;
    __syncthreads();
    if (threadIdx.x == 0) {
        float s = 0.f;
#pragma unroll
        for (int i = 0; i < 8; i++) s += red[i];
        g_regpart[blockIdx.x] = s;
    }
    // entries for this bucket: warp ty takes e = o0+ty, o0+ty+8, ...
    int o0 = g_boff[blockIdx.x];
    int o1 = g_boff[blockIdx.x + 1];
    for (int e = o0 + ty; e < o1; e += 8) {
        int ent = g_bent[e];
        int c   = ent >> 16;
        int idx = ent & 0xFFFF;         // b*11 + v
        int b   = idx / 11;
        const float* trow = &g_T[b * DEm];
        float acc = 0.f;
#pragma unroll
        for (int i = 0; i < 8; i++) {
            int d = tx + i * 32;
            acc += trow[d] * tile[d][c];
        }
        acc = warpSum(acc);
        if (tx == 0) g_dots[idx] = acc;
    }
}

// K7: per-batch loss from 11 dots
__global__ void __launch_bounds__(128)
k_loss() {
    int b = blockIdx.x * 128 + threadIdx.x;     // 32 blocks x 128
    const float* d = &g_dots[b * 11];
    float lp = 10.f * fminf(log_sig(d[0]), -1.0005003e-3f);   // log(0.999)
    float ns = 0.f;
#pragma unroll
    for (int z = 0; z < NZ; z++)
        ns += fmaxf(log_sig(-d[1 + z]), -4.60517019f);        // log(0.01)
    g_lpw[b] = 0.55f * (lp + ns);                             // (Z+1)/(2Z)
}

// K8: final reduce (double)
__global__ void __launch_bounds__(256) k_final(float* __restrict__ out) {
    int t = threadIdx.x;
    double a = 0.0, r = 0.0;
    for (int i = t; i < NB;        i += 256) a += (double)g_lpw[i];
    for (int i = t; i < NBKT;      i += 256) r += (double)g_regpart[i];
    for (int i = t; i < PT_BLOCKS; i += 256) r += (double)g_projsq[i];
    __shared__ double sa[256], sr[256];
    sa[t] = a; sr[t] = r;
    __syncthreads();
    for (int o = 128; o; o >>= 1) {
        if (t < o) { sa[t] += sa[t + o]; sr[t] += sr[t + o]; }
        __syncthreads();
    }
    if (t == 0)
        out[0] = (float)(sa[0] / (double)NB + (0.01 / (2.0 * NB)) * sr[0]);
}

// ---------------------------------------------------------------------------
extern "C" void kernel_launch(void* const* d_in, const int* in_sizes, int n_in,
                              void* d_out, int out_size) {
    const float* rv       = (const float*)d_in[0];
    const float* rd       = (const float*)d_in[1];
    const float* proj     = (const float*)d_in[2];
    const float* beta     = (const float*)d_in[3];
    const int*   word_ids = (const int*)d_in[4];
    const int*   doc_ids  = (const int*)d_in[5];
    const int*   neg_ids  = (const int*)d_in[6];

    // CSR bucket build (depends only on ids; tiny)
    k_bzero <<<(NBKT + 255) / 256, 256>>>();
    k_bcount<<<(NENT + 255) / 256, 256>>>(doc_ids, neg_ids);
    k_bscan <<<1, 1024>>>();
    k_bfill <<<(NENT + 255) / 256, 256>>>(doc_ids, neg_ids);

    // Main chain (single stream, no cross-stream joins)
    k_pt    <<<PT_BLOCKS, 256>>>(proj);
    k_trv   <<<dim3((NV + 31) / 32, (WE + 31) / 32), dim3(32, 8)>>>(rv);
    k_gather<<<NB, 320>>>(word_ids);
    k_gemm  <<<dim3(NB / 64, DEm / 64), 256>>>();
    k_stats1<<<ST_BLOCKS, 256>>>();
    k_stats2<<<1, 256>>>();
    k_tmat  <<<NB, 256>>>(beta);
    k_fused <<<NBKT, 256>>>(rd);
    k_loss  <<<NB / 128, 128>>>();
    k_final <<<1, 256>>>((float*)d_out);
}

// round 11
// speedup vs baseline: 1.4812x; 1.4812x over previous
#include <cuda_runtime.h>
#include <math.h>

// Problem constants
#define WE   300      // word embedding dim
#define DEm  256      // doc embedding dim
#define NV   50000    // vocab
#define NDn  100000   // num docs
#define NB   4096     // batch
#define NGw  10       // words per bag
#define NZ   10       // negatives
#define NENT (NB * 11)      // 45056 (b, slot) -> doc entries
#define NBKT (NDn / 32)     // 3125 doc buckets (32 cols each)

// ---------------- scratch (device globals; no allocation) ----------------
__device__ __align__(16) float g_rvT[(size_t)NV * WE];   // 60 MB
__device__ __align__(16) float g_gNT[NB * WE];           // 4096 x 300
__device__ __align__(16) float g_Ct[NB * DEm];           // t_pre^T: 4096 x 256
__device__ int   g_bcnt[NBKT];
__device__ int   g_boff[NBKT + 1];
__device__ int   g_bcur[NBKT];
__device__ int   g_bent[NENT];
__device__ float g_dots[NENT];
__device__ float g_sum [DEm];      // atomic stats accumulators
__device__ float g_ssum[DEm];
__device__ float g_lpw[NB];
__device__ float g_regpart[NBKT];

__device__ __forceinline__ float warpSum(float v) {
#pragma unroll
    for (int o = 16; o; o >>= 1) v += __shfl_down_sync(0xffffffffu, v, o);
    return v;
}
__device__ __forceinline__ float log_sig(float x) {
    return (x >= 0.f) ? -log1pf(expf(-x)) : x - log1pf(expf(x));
}

// ================= CSR bucket build (side stream; ids only) ================
__global__ void __launch_bounds__(256) k_bzero() {
    int i = blockIdx.x * 256 + threadIdx.x;
    if (i < NBKT) g_bcnt[i] = 0;
}
__global__ void __launch_bounds__(256)
k_bcount(const int* __restrict__ doc_ids, const int* __restrict__ neg_ids) {
    int i = blockIdx.x * 256 + threadIdx.x;
    if (i >= NENT) return;
    int doc = (i < NB) ? doc_ids[i] : neg_ids[i - NB];
    atomicAdd(&g_bcnt[doc >> 5], 1);
}
__global__ void __launch_bounds__(1024) k_bscan() {
    const int T = 1024, CH = (NBKT + T - 1) / T;   // 4
    __shared__ int s[T];
    int t = threadIdx.x;
    int base = t * CH;
    int sum = 0;
#pragma unroll 1
    for (int i = 0; i < CH; i++) {
        int v = base + i;
        if (v < NBKT) sum += g_bcnt[v];
    }
    s[t] = sum;
    __syncthreads();
    for (int o = 1; o < T; o <<= 1) {
        int x = (t >= o) ? s[t - o] : 0;
        __syncthreads();
        s[t] += x;
        __syncthreads();
    }
    int run = s[t] - sum;
#pragma unroll 1
    for (int i = 0; i < CH; i++) {
        int v = base + i;
        if (v < NBKT) {
            g_boff[v] = run;
            g_bcur[v] = run;
            run += g_bcnt[v];
        }
    }
    if (t == T - 1) g_boff[NBKT] = s[T - 1];
}
__global__ void __launch_bounds__(256)
k_bfill(const int* __restrict__ doc_ids, const int* __restrict__ neg_ids) {
    int i = blockIdx.x * 256 + threadIdx.x;
    if (i >= NENT) return;
    int b, v, doc;
    if (i < NB) { b = i; v = 0; doc = doc_ids[i]; }
    else {
        int j = i - NB;
        b = j / NZ; v = 1 + (j % NZ); doc = neg_ids[j];
    }
    int pos = atomicAdd(&g_bcur[doc >> 5], 1);
    g_bent[pos] = ((doc & 31) << 16) | (b * 11 + v);
}

// ================= main chain ==============================================
// K1: transpose rv (300 x 50000 -> 50000 x 300)
__global__ void __launch_bounds__(256) k_trv(const float* __restrict__ rv) {
    __shared__ float t[32][33];
    int x0 = blockIdx.x * 32, y0 = blockIdx.y * 32;
    int tx = threadIdx.x, ty = threadIdx.y;       // (32, 8)
#pragma unroll
    for (int j = 0; j < 32; j += 8) {
        int r = y0 + ty + j, c = x0 + tx;
        t[ty + j][tx] = (r < WE && c < NV) ? rv[(size_t)r * NV + c] : 0.f;
    }
    __syncthreads();
#pragma unroll
    for (int j = 0; j < 32; j += 8) {
        int c = x0 + ty + j, r = y0 + tx;
        if (c < NV && r < WE) g_rvT[(size_t)c * WE + r] = t[tx][ty + j];
    }
}

// K2: gather 10 word rows of rvT, mean, L2-normalize. Blocks 0/1 also zero
// the stats accumulators (safe: k_gemm launches strictly after this kernel).
__global__ void __launch_bounds__(320) k_gather(const int* __restrict__ word_ids) {
    int b = blockIdx.x;
    int tid = threadIdx.x;                 // 320 threads
    if (b == 0 && tid < DEm) g_sum[tid]  = 0.f;
    if (b == 1 && tid < DEm) g_ssum[tid] = 0.f;
    __shared__ int   wid[NGw];
    __shared__ float red[10];
    __shared__ float rinv;
    if (tid < NGw) wid[tid] = word_ids[b * NGw + tid];
    __syncthreads();
    float g = 0.f;
    if (tid < WE) {
#pragma unroll
        for (int j = 0; j < NGw; j++) g += __ldg(&g_rvT[(size_t)wid[j] * WE + tid]);
        g *= 0.1f;
    }
    float s = warpSum(g * g);
    if ((tid & 31) == 0) red[tid >> 5] = s;
    __syncthreads();
    if (tid == 0) {
        float t = 0.f;
#pragma unroll
        for (int i = 0; i < 10; i++) t += red[i];
        rinv = rsqrtf(t);
    }
    __syncthreads();
    if (tid < WE) g_gNT[b * WE + tid] = g * rinv;
}

// K3: SGEMM Ct[n][m] = sum_k gNT[n][k] * proj[m][k], direct proj read,
// fused per-m partial stats (sum, sumsq over n) via atomics.
__global__ void __launch_bounds__(256) k_gemm(const float* __restrict__ proj) {
    __shared__ float Asm[20][68];   // [k][n]
    __shared__ float Bsm[20][68];   // [k][m]
    int tid = threadIdx.x;
    int tm = tid >> 4, tn = tid & 15;
    int n0 = blockIdx.x * 64, m0 = blockIdx.y * 64;
    float acc[4][4] = {};           // [mj][ni]
    for (int k0 = 0; k0 < WE; k0 += 20) {
        for (int i = tid; i < 320; i += 256) {
            int row = i / 5, kq = i % 5;
            float4 v = *(const float4*)&g_gNT[(n0 + row) * WE + k0 + kq * 4];
            Asm[kq * 4 + 0][row] = v.x;
            Asm[kq * 4 + 1][row] = v.y;
            Asm[kq * 4 + 2][row] = v.z;
            Asm[kq * 4 + 3][row] = v.w;
            float4 w = *(const float4*)&proj[(size_t)(m0 + row) * WE + k0 + kq * 4];
            Bsm[kq * 4 + 0][row] = w.x;
            Bsm[kq * 4 + 1][row] = w.y;
            Bsm[kq * 4 + 2][row] = w.z;
            Bsm[kq * 4 + 3][row] = w.w;
        }
        __syncthreads();
#pragma unroll
        for (int k = 0; k < 20; k++) {
            float4 a = *(const float4*)&Asm[k][tm * 4];   // n values
            float4 b = *(const float4*)&Bsm[k][tn * 4];   // m values
            float an[4] = {a.x, a.y, a.z, a.w};
            float bm[4] = {b.x, b.y, b.z, b.w};
#pragma unroll
            for (int j = 0; j < 4; j++)
#pragma unroll
                for (int i = 0; i < 4; i++) acc[j][i] += bm[j] * an[i];
        }
        __syncthreads();
    }
#pragma unroll
    for (int i = 0; i < 4; i++) {
        int n = n0 + tm * 4 + i;
        *(float4*)&g_Ct[n * DEm + m0 + tn * 4] =
            make_float4(acc[0][i], acc[1][i], acc[2][i], acc[3][i]);
    }
    // fused stats: per-m partials over this block's 64 n values
    __shared__ float redS[16][64];
    __shared__ float redQ[16][64];
#pragma unroll
    for (int j = 0; j < 4; j++) {
        float s = acc[j][0] + acc[j][1] + acc[j][2] + acc[j][3];
        float q = acc[j][0] * acc[j][0] + acc[j][1] * acc[j][1]
                + acc[j][2] * acc[j][2] + acc[j][3] * acc[j][3];
        redS[tm][tn * 4 + j] = s;
        redQ[tm][tn * 4 + j] = q;
    }
    __syncthreads();
    if (tid < 64) {
        float s = 0.f, q = 0.f;
#pragma unroll
        for (int w = 0; w < 16; w++) { s += redS[w][tid]; q += redQ[w][tid]; }
        atomicAdd(&g_sum [m0 + tid], s);
        atomicAdd(&g_ssum[m0 + tid], q);
    }
}

// K4: FUSED rd pass — one coalesced read of rd; sum(rd^2) partials; inline
// batchnorm from atomic stats; all dot-products for this bucket's entries.
__global__ void __launch_bounds__(256)
k_fused(const float* __restrict__ rd, const float* __restrict__ beta) {
    __shared__ float tile[DEm][33];     // [d][c], conflict-free both phases
    __shared__ float sMean[DEm], sFac[DEm], sBeta[DEm];
    __shared__ float red[8];
    int c0 = blockIdx.x * 32;
    int tx = threadIdx.x & 31;
    int ty = threadIdx.x >> 5;          // warp id 0..7
    float ss = 0.f;
#pragma unroll
    for (int d0 = 0; d0 < DEm; d0 += 8) {
        float v = __ldg(&rd[(size_t)(d0 + ty) * NDn + c0 + tx]);
        tile[d0 + ty][tx] = v;
        ss += v * v;
    }
    // norm params (256 threads, one d each)
    {
        int d = threadIdx.x;
        float s = g_sum[d], q = g_ssum[d];
        float mean = s * (1.0f / NB);
        float var  = fmaxf((q - (float)NB * mean * mean) * (1.0f / (NB - 1)), 0.f);
        sMean[d] = mean;
        sFac[d]  = rsqrtf(sqrtf(var));   // 1/sqrt(std), std ddof=1
        sBeta[d] = beta[d];
    }
    ss = warpSum(ss);
    if (tx == 0) red[ty] = ss;
    __syncthreads();
    if (threadIdx.x == 0) {
        float s = 0.f;
#pragma unroll
        for (int i = 0; i < 8; i++) s += red[i];
        g_regpart[blockIdx.x] = s;
    }
    // entries for this bucket: warp ty takes e = o0+ty, o0+ty+8, ...
    int o0 = g_boff[blockIdx.x];
    int o1 = g_boff[blockIdx.x + 1];
    for (int e = o0 + ty; e < o1; e += 8) {
        int ent = g_bent[e];
        int c   = ent >> 16;
        int idx = ent & 0xFFFF;         // b*11 + v
        int b   = idx / 11;
        const float* crow = &g_Ct[b * DEm];
        float acc = 0.f;
#pragma unroll
        for (int i = 0; i < 8; i++) {
            int d = tx + i * 32;
            float tv = fminf(fmaxf((crow[d] - sMean[d]) * sFac[d] + sBeta[d],
                                   -1.f), 1.f);
            acc += tv * tile[d][c];
        }
        acc = warpSum(acc);
        if (tx == 0) g_dots[idx] = acc;
    }
}

// K5: per-batch loss from 11 dots
__global__ void __launch_bounds__(128) k_loss() {
    int b = blockIdx.x * 128 + threadIdx.x;     // 32 blocks x 128
    const float* d = &g_dots[b * 11];
    float lp = 10.f * fminf(log_sig(d[0]), -1.0005003e-3f);   // log(0.999)
    float ns = 0.f;
#pragma unroll
    for (int z = 0; z < NZ; z++)
        ns += fmaxf(log_sig(-d[1 + z]), -4.60517019f);        // log(0.01)
    g_lpw[b] = 0.55f * (lp + ns);                             // (Z+1)/(2Z)
}

// K6: final reduce (double) + sum(proj^2) inline
__global__ void __launch_bounds__(256)
k_final(const float* __restrict__ proj, float* __restrict__ out) {
    int t = threadIdx.x;
    double a = 0.0, r = 0.0;
    for (int i = t; i < NB;   i += 256) a += (double)g_lpw[i];
    for (int i = t; i < NBKT; i += 256) r += (double)g_regpart[i];
    {
        float ps = 0.f;
        for (int i = t; i < WE * DEm; i += 256) {
            float v = proj[i];
            ps += v * v;
        }
        r += (double)ps;
    }
    __shared__ double sa[256], sr[256];
    sa[t] = a; sr[t] = r;
    __syncthreads();
    for (int o = 128; o; o >>= 1) {
        if (t < o) { sa[t] += sa[t + o]; sr[t] += sr[t + o]; }
        __syncthreads();
    }
    if (t == 0)
        out[0] = (float)(sa[0] / (double)NB + (0.01 / (2.0 * NB)) * sr[0]);
}

// ---------------------------------------------------------------------------
static cudaStream_t g_s2;
static cudaEvent_t  g_e1, g_e2;
namespace {
struct _Init {
    _Init() {
        cudaStreamCreateWithFlags(&g_s2, cudaStreamNonBlocking);
        cudaEventCreateWithFlags(&g_e1, cudaEventDisableTiming);
        cudaEventCreateWithFlags(&g_e2, cudaEventDisableTiming);
    }
} _init;
}

extern "C" void kernel_launch(void* const* d_in, const int* in_sizes, int n_in,
                              void* d_out, int out_size) {
    const float* rv       = (const float*)d_in[0];
    const float* rd       = (const float*)d_in[1];
    const float* proj     = (const float*)d_in[2];
    const float* beta     = (const float*)d_in[3];
    const int*   word_ids = (const int*)d_in[4];
    const int*   doc_ids  = (const int*)d_in[5];
    const int*   neg_ids  = (const int*)d_in[6];

    // Side stream: CSR bucket build over doc/neg ids, overlapped with trv.
    cudaEventRecord(g_e1, 0);
    cudaStreamWaitEvent(g_s2, g_e1, 0);
    k_bzero <<<(NBKT + 255) / 256, 256, 0, g_s2>>>();
    k_bcount<<<(NENT + 255) / 256, 256, 0, g_s2>>>(doc_ids, neg_ids);
    k_bscan <<<1, 1024, 0, g_s2>>>();
    k_bfill <<<(NENT + 255) / 256, 256, 0, g_s2>>>(doc_ids, neg_ids);
    cudaEventRecord(g_e2, g_s2);

    // Main chain: 6 kernels
    k_trv   <<<dim3((NV + 31) / 32, (WE + 31) / 32), dim3(32, 8)>>>(rv);
    k_gather<<<NB, 320>>>(word_ids);
    k_gemm  <<<dim3(NB / 64, DEm / 64), 256>>>(proj);
    cudaStreamWaitEvent(0, g_e2, 0);   // join: fused needs buckets
    k_fused <<<NBKT, 256>>>(rd, beta);
    k_loss  <<<NB / 128, 128>>>();
    k_final <<<1, 256>>>(proj, (float*)d_out);
}

// round 12
// speedup vs baseline: 1.6214x; 1.0946x over previous
#include <cuda_runtime.h>
#include <cuda_fp16.h>
#include <math.h>

// Problem constants
#define WE   300      // word embedding dim
#define WE2  320      // padded (fp16 staging) word dim, mult of 64
#define DEm  256      // doc embedding dim
#define NV   50000    // vocab
#define NDn  100000   // num docs
#define NB   4096     // batch
#define NGw  10       // words per bag
#define NZ   10       // negatives
#define NENT (NB * 11)      // 45056 (b, slot) -> doc entries
#define NBKT (NDn / 32)     // 3125 doc buckets (32 cols each)

// ---------------- scratch (device globals; no allocation) ----------------
__device__ __align__(16) __half g_rvT16[(size_t)NV * WE2];  // 32 MB fp16 staging
__device__ __align__(16) float g_gNT[NB * WE];              // 4096 x 300
__device__ __align__(16) float g_Ct[NB * DEm];              // t_pre^T: 4096 x 256
__device__ int   g_bcnt[NBKT];
__device__ int   g_boff[NBKT + 1];
__device__ int   g_bcur[NBKT];
__device__ int   g_bent[NENT];
__device__ float g_dots[NENT];
__device__ float g_sum [DEm];      // atomic stats accumulators
__device__ float g_ssum[DEm];
__device__ float g_lpw[NB];
__device__ float g_regpart[NBKT];

__device__ __forceinline__ float warpSum(float v) {
#pragma unroll
    for (int o = 16; o; o >>= 1) v += __shfl_down_sync(0xffffffffu, v, o);
    return v;
}
__device__ __forceinline__ float log_sig(float x) {
    return (x >= 0.f) ? -log1pf(expf(-x)) : x - log1pf(expf(x));
}

// ================= CSR bucket build (side stream; ids only) ================
__global__ void __launch_bounds__(256) k_bzero() {
    int i = blockIdx.x * 256 + threadIdx.x;
    if (i < NBKT) g_bcnt[i] = 0;
}
__global__ void __launch_bounds__(256)
k_bcount(const int* __restrict__ doc_ids, const int* __restrict__ neg_ids) {
    int i = blockIdx.x * 256 + threadIdx.x;
    if (i >= NENT) return;
    int doc = (i < NB) ? doc_ids[i] : neg_ids[i - NB];
    atomicAdd(&g_bcnt[doc >> 5], 1);
}
__global__ void __launch_bounds__(1024) k_bscan() {
    const int T = 1024, CH = (NBKT + T - 1) / T;   // 4
    __shared__ int s[T];
    int t = threadIdx.x;
    int base = t * CH;
    int sum = 0;
#pragma unroll 1
    for (int i = 0; i < CH; i++) {
        int v = base + i;
        if (v < NBKT) sum += g_bcnt[v];
    }
    s[t] = sum;
    __syncthreads();
    for (int o = 1; o < T; o <<= 1) {
        int x = (t >= o) ? s[t - o] : 0;
        __syncthreads();
        s[t] += x;
        __syncthreads();
    }
    int run = s[t] - sum;
#pragma unroll 1
    for (int i = 0; i < CH; i++) {
        int v = base + i;
        if (v < NBKT) {
            g_boff[v] = run;
            g_bcur[v] = run;
            run += g_bcnt[v];
        }
    }
    if (t == T - 1) g_boff[NBKT] = s[T - 1];
}
__global__ void __launch_bounds__(256)
k_bfill(const int* __restrict__ doc_ids, const int* __restrict__ neg_ids) {
    int i = blockIdx.x * 256 + threadIdx.x;
    if (i >= NENT) return;
    int b, v, doc;
    if (i < NB) { b = i; v = 0; doc = doc_ids[i]; }
    else {
        int j = i - NB;
        b = j / NZ; v = 1 + (j % NZ); doc = neg_ids[j];
    }
    int pos = atomicAdd(&g_bcur[doc >> 5], 1);
    g_bent[pos] = ((doc & 31) << 16) | (b * 11 + v);
}

// ================= main chain ==============================================
// K1: transpose rv (300 x 50000) -> fp16 rvT16 (50000 x 320, zero-padded).
// 64-k x 32-v tiles; stores are half2 -> full 128B sectors per warp.
__global__ void __launch_bounds__(256) k_trv(const float* __restrict__ rv) {
    __shared__ float t[64][33];
    int x0 = blockIdx.x * 32;      // v base
    int y0 = blockIdx.y * 64;      // k base (0,64,128,192,256)
    int tx = threadIdx.x & 31, ty = threadIdx.x >> 5;   // 32 x 8
#pragma unroll
    for (int j = 0; j < 64; j += 8) {
        int k = y0 + ty + j, v = x0 + tx;
        t[ty + j][tx] = (k < WE && v < NV) ? rv[(size_t)k * NV + v] : 0.f;
    }
    __syncthreads();
#pragma unroll
    for (int j = 0; j < 32; j += 8) {
        int v = x0 + ty + j;
        if (v < NV) {
            __half2 h = __halves2half2(__float2half(t[2 * tx][ty + j]),
                                       __float2half(t[2 * tx + 1][ty + j]));
            *(__half2*)&g_rvT16[(size_t)v * WE2 + y0 + 2 * tx] = h;
        }
    }
}

// K2: gather 10 word rows (half2), mean, L2-normalize. Blocks 0/1 zero the
// stats accumulators (safe: k_gemm launches strictly after this kernel).
__global__ void __launch_bounds__(256) k_gather(const int* __restrict__ word_ids) {
    int b = blockIdx.x;
    int tid = threadIdx.x;                 // 256 threads; tid<160 load half2
    if (b == 0 && tid < DEm) g_sum[tid]  = 0.f;
    if (b == 1 && tid < DEm) g_ssum[tid] = 0.f;
    __shared__ int   wid[NGw];
    __shared__ float red[8];
    __shared__ float rinv;
    if (tid < NGw) wid[tid] = word_ids[b * NGw + tid];
    __syncthreads();
    float gx = 0.f, gy = 0.f;
    if (tid < 160) {
#pragma unroll
        for (int j = 0; j < NGw; j++) {
            __half2 h = *(const __half2*)&g_rvT16[(size_t)wid[j] * WE2 + 2 * tid];
            float2 f = __half22float2(h);
            gx += f.x; gy += f.y;
        }
        gx *= 0.1f; gy *= 0.1f;
    }
    float s = warpSum(gx * gx + gy * gy);
    if ((tid & 31) == 0) red[tid >> 5] = s;
    __syncthreads();
    if (tid == 0) {
        float t = 0.f;
#pragma unroll
        for (int i = 0; i < 8; i++) t += red[i];
        rinv = rsqrtf(t);
    }
    __syncthreads();
    if (tid < 150)
        *(float2*)&g_gNT[b * WE + 2 * tid] = make_float2(gx * rinv, gy * rinv);
}

// K3: SGEMM Ct[n][m] = sum_k gNT[n][k] * proj[m][k], direct proj read,
// fused per-m partial stats (sum, sumsq over n) via atomics.
__global__ void __launch_bounds__(256) k_gemm(const float* __restrict__ proj) {
    __shared__ float Asm[20][68];   // [k][n]
    __shared__ float Bsm[20][68];   // [k][m]
    int tid = threadIdx.x;
    int tm = tid >> 4, tn = tid & 15;
    int n0 = blockIdx.x * 64, m0 = blockIdx.y * 64;
    float acc[4][4] = {};           // [mj][ni]
    for (int k0 = 0; k0 < WE; k0 += 20) {
        for (int i = tid; i < 320; i += 256) {
            int row = i / 5, kq = i % 5;
            float4 v = *(const float4*)&g_gNT[(n0 + row) * WE + k0 + kq * 4];
            Asm[kq * 4 + 0][row] = v.x;
            Asm[kq * 4 + 1][row] = v.y;
            Asm[kq * 4 + 2][row] = v.z;
            Asm[kq * 4 + 3][row] = v.w;
            float4 w = *(const float4*)&proj[(size_t)(m0 + row) * WE + k0 + kq * 4];
            Bsm[kq * 4 + 0][row] = w.x;
            Bsm[kq * 4 + 1][row] = w.y;
            Bsm[kq * 4 + 2][row] = w.z;
            Bsm[kq * 4 + 3][row] = w.w;
        }
        __syncthreads();
#pragma unroll
        for (int k = 0; k < 20; k++) {
            float4 a = *(const float4*)&Asm[k][tm * 4];   // n values
            float4 b = *(const float4*)&Bsm[k][tn * 4];   // m values
            float an[4] = {a.x, a.y, a.z, a.w};
            float bm[4] = {b.x, b.y, b.z, b.w};
#pragma unroll
            for (int j = 0; j < 4; j++)
#pragma unroll
                for (int i = 0; i < 4; i++) acc[j][i] += bm[j] * an[i];
        }
        __syncthreads();
    }
#pragma unroll
    for (int i = 0; i < 4; i++) {
        int n = n0 + tm * 4 + i;
        *(float4*)&g_Ct[n * DEm + m0 + tn * 4] =
            make_float4(acc[0][i], acc[1][i], acc[2][i], acc[3][i]);
    }
    // fused stats: per-m partials over this block's 64 n values
    __shared__ float redS[16][64];
    __shared__ float redQ[16][64];
#pragma unroll
    for (int j = 0; j < 4; j++) {
        float s = acc[j][0] + acc[j][1] + acc[j][2] + acc[j][3];
        float q = acc[j][0] * acc[j][0] + acc[j][1] * acc[j][1]
                + acc[j][2] * acc[j][2] + acc[j][3] * acc[j][3];
        redS[tm][tn * 4 + j] = s;
        redQ[tm][tn * 4 + j] = q;
    }
    __syncthreads();
    if (tid < 64) {
        float s = 0.f, q = 0.f;
#pragma unroll
        for (int w = 0; w < 16; w++) { s += redS[w][tid]; q += redQ[w][tid]; }
        atomicAdd(&g_sum [m0 + tid], s);
        atomicAdd(&g_ssum[m0 + tid], q);
    }
}

// K4: FUSED rd pass — one coalesced read of rd; sum(rd^2) partials; inline
// batchnorm from atomic stats; all dot-products for this bucket's entries.
__global__ void __launch_bounds__(256)
k_fused(const float* __restrict__ rd, const float* __restrict__ beta) {
    __shared__ float tile[DEm][33];     // [d][c], conflict-free both phases
    __shared__ float sMean[DEm], sFac[DEm], sBeta[DEm];
    __shared__ float red[8];
    int c0 = blockIdx.x * 32;
    int tx = threadIdx.x & 31;
    int ty = threadIdx.x >> 5;          // warp id 0..7
    float ss = 0.f;
#pragma unroll
    for (int d0 = 0; d0 < DEm; d0 += 8) {
        float v = __ldg(&rd[(size_t)(d0 + ty) * NDn + c0 + tx]);
        tile[d0 + ty][tx] = v;
        ss += v * v;
    }
    // norm params (256 threads, one d each)
    {
        int d = threadIdx.x;
        float s = g_sum[d], q = g_ssum[d];
        float mean = s * (1.0f / NB);
        float var  = fmaxf((q - (float)NB * mean * mean) * (1.0f / (NB - 1)), 0.f);
        sMean[d] = mean;
        sFac[d]  = rsqrtf(sqrtf(var));   // 1/sqrt(std), std ddof=1
        sBeta[d] = beta[d];
    }
    ss = warpSum(ss);
    if (tx == 0) red[ty] = ss;
    __syncthreads();
    if (threadIdx.x == 0) {
        float s = 0.f;
#pragma unroll
        for (int i = 0; i < 8; i++) s += red[i];
        g_regpart[blockIdx.x] = s;
    }
    // entries for this bucket: warp ty takes e = o0+ty, o0+ty+8, ...
    int o0 = g_boff[blockIdx.x];
    int o1 = g_boff[blockIdx.x + 1];
    for (int e = o0 + ty; e < o1; e += 8) {
        int ent = g_bent[e];
        int c   = ent >> 16;
        int idx = ent & 0xFFFF;         // b*11 + v
        int b   = idx / 11;
        const float* crow = &g_Ct[b * DEm];
        float acc = 0.f;
#pragma unroll
        for (int i = 0; i < 8; i++) {
            int d = tx + i * 32;
            float tv = fminf(fmaxf((crow[d] - sMean[d]) * sFac[d] + sBeta[d],
                                   -1.f), 1.f);
            acc += tv * tile[d][c];
        }
        acc = warpSum(acc);
        if (tx == 0) g_dots[idx] = acc;
    }
}

// K5: per-batch loss from 11 dots (32 blocks — MUFU spread across SMs)
__global__ void __launch_bounds__(128) k_loss() {
    int b = blockIdx.x * 128 + threadIdx.x;     // 32 blocks x 128
    const float* d = &g_dots[b * 11];
    float lp = 10.f * fminf(log_sig(d[0]), -1.0005003e-3f);   // log(0.999)
    float ns = 0.f;
#pragma unroll
    for (int z = 0; z < NZ; z++)
        ns += fmaxf(log_sig(-d[1 + z]), -4.60517019f);        // log(0.01)
    g_lpw[b] = 0.55f * (lp + ns);                             // (Z+1)/(2Z)
}

// K6: final reduce (double) + sum(proj^2) inline
__global__ void __launch_bounds__(256)
k_final(const float* __restrict__ proj, float* __restrict__ out) {
    int t = threadIdx.x;
    double a = 0.0, r = 0.0;
    for (int i = t; i < NB;   i += 256) a += (double)g_lpw[i];
    for (int i = t; i < NBKT; i += 256) r += (double)g_regpart[i];
    {
        float ps = 0.f;
        for (int i = t; i < WE * DEm; i += 256) {
            float v = proj[i];
            ps += v * v;
        }
        r += (double)ps;
    }
    __shared__ double sa[256], sr[256];
    sa[t] = a; sr[t] = r;
    __syncthreads();
    for (int o = 128; o; o >>= 1) {
        if (t < o) { sa[t] += sa[t + o]; sr[t] += sr[t + o]; }
        __syncthreads();
    }
    if (t == 0)
        out[0] = (float)(sa[0] / (double)NB + (0.01 / (2.0 * NB)) * sr[0]);
}

// ---------------------------------------------------------------------------
static cudaStream_t g_s2;
static cudaEvent_t  g_e1, g_e2;
namespace {
struct _Init {
    _Init() {
        cudaStreamCreateWithFlags(&g_s2, cudaStreamNonBlocking);
        cudaEventCreateWithFlags(&g_e1, cudaEventDisableTiming);
        cudaEventCreateWithFlags(&g_e2, cudaEventDisableTiming);
    }
} _init;
}

extern "C" void kernel_launch(void* const* d_in, const int* in_sizes, int n_in,
                              void* d_out, int out_size) {
    const float* rv       = (const float*)d_in[0];
    const float* rd       = (const float*)d_in[1];
    const float* proj     = (const float*)d_in[2];
    const float* beta     = (const float*)d_in[3];
    const int*   word_ids = (const int*)d_in[4];
    const int*   doc_ids  = (const int*)d_in[5];
    const int*   neg_ids  = (const int*)d_in[6];

    // Side stream: CSR bucket build over doc/neg ids, overlapped with trv.
    cudaEventRecord(g_e1, 0);
    cudaStreamWaitEvent(g_s2, g_e1, 0);
    k_bzero <<<(NBKT + 255) / 256, 256, 0, g_s2>>>();
    k_bcount<<<(NENT + 255) / 256, 256, 0, g_s2>>>(doc_ids, neg_ids);
    k_bscan <<<1, 1024, 0, g_s2>>>();
    k_bfill <<<(NENT + 255) / 256, 256, 0, g_s2>>>(doc_ids, neg_ids);
    cudaEventRecord(g_e2, g_s2);

    // Main chain: 6 kernels
    k_trv   <<<dim3((NV + 31) / 32, WE2 / 64), 256>>>(rv);
    k_gather<<<NB, 256>>>(word_ids);
    k_gemm  <<<dim3(NB / 64, DEm / 64), 256>>>(proj);
    cudaStreamWaitEvent(0, g_e2, 0);   // join: fused needs buckets
    k_fused <<<NBKT, 256>>>(rd, beta);
    k_loss  <<<NB / 128, 128>>>();
    k_final <<<1, 256>>>(proj, (float*)d_out);
}